// round 13
// baseline (speedup 1.0000x reference)
#include <cuda_runtime.h>
#include <cuda_fp16.h>
#include <cstdint>

#define CC 128
#define HH 128
#define MM (384*384)

__device__ __align__(16) __half g_left [(size_t)HH*MM];   // [h][i*384+k]
__device__ __align__(16) __half g_right[(size_t)HH*MM];   // [h][k*384+j]
__device__ __align__(16) __half g_gate [(size_t)HH*MM];   // [h][i*384+j]; k2 overwrites in-place
__device__ __align__(16) __half g_WL [128*256];
__device__ __align__(16) __half g_WR [128*128];
__device__ __align__(16) __half g_WG [128*128];
__device__ __align__(16) __half g_WoT[128*128];
__device__ float g_bL[128], g_bR[128], g_bG[128];

__device__ __forceinline__ void mma16(float* d, uint32_t a0,uint32_t a1,uint32_t a2,uint32_t a3,
                                      uint32_t b0,uint32_t b1){
    asm volatile(
      "mma.sync.aligned.m16n8k16.row.col.f32.f16.f16.f32 "
      "{%0,%1,%2,%3},{%4,%5,%6,%7},{%8,%9},{%0,%1,%2,%3};\n"
      : "+f"(d[0]),"+f"(d[1]),"+f"(d[2]),"+f"(d[3])
      : "r"(a0),"r"(a1),"r"(a2),"r"(a3),"r"(b0),"r"(b1));
}
__device__ __forceinline__ void cp16h(__half* s, const __half* g){
    unsigned sa = (unsigned)__cvta_generic_to_shared(s);
    asm volatile("cp.async.ca.shared.global [%0], [%1], 16;" :: "r"(sa), "l"(g) : "memory");
}
__device__ __forceinline__ void cp16f(float* s, const float* g){
    unsigned sa = (unsigned)__cvta_generic_to_shared(s);
    asm volatile("cp.async.ca.shared.global [%0], [%1], 16;" :: "r"(sa), "l"(g) : "memory");
}
__device__ __forceinline__ void cp_commit(){ asm volatile("cp.async.commit_group;" ::: "memory"); }
__device__ __forceinline__ void cp_wait1(){ asm volatile("cp.async.wait_group 1;" ::: "memory"); }
__device__ __forceinline__ void cp_wait0(){ asm volatile("cp.async.wait_group 0;" ::: "memory"); }
__device__ __forceinline__ void ldm_x4(uint32_t& r0, uint32_t& r1, uint32_t& r2, uint32_t& r3, uint32_t sa){
    asm volatile("ldmatrix.sync.aligned.m8n8.x4.shared.b16 {%0,%1,%2,%3}, [%4];"
                 : "=r"(r0),"=r"(r1),"=r"(r2),"=r"(r3) : "r"(sa));
}
__device__ __forceinline__ void ldm_x4t(uint32_t& r0, uint32_t& r1, uint32_t& r2, uint32_t& r3, uint32_t sa){
    asm volatile("ldmatrix.sync.aligned.m8n8.x4.trans.shared.b16 {%0,%1,%2,%3}, [%4];"
                 : "=r"(r0),"=r"(r1),"=r"(r2),"=r"(r3) : "r"(sa));
}
__device__ __forceinline__ void ldm_x2(uint32_t& r0, uint32_t& r1, uint32_t sa){
    asm volatile("ldmatrix.sync.aligned.m8n8.x2.shared.b16 {%0,%1}, [%2];"
                 : "=r"(r0),"=r"(r1) : "r"(sa));
}
__device__ __forceinline__ void ldm_x2t(uint32_t& r0, uint32_t& r1, uint32_t sa){
    asm volatile("ldmatrix.sync.aligned.m8n8.x2.trans.shared.b16 {%0,%1}, [%2];"
                 : "=r"(r0),"=r"(r1) : "r"(sa));
}

// ---------------- prep ----------------
__global__ void prep_kernel(const float* __restrict__ Wl, const float* __restrict__ bl,
                            const float* __restrict__ Wr, const float* __restrict__ br,
                            const float* __restrict__ Wg, const float* __restrict__ bg,
                            const float* __restrict__ We, const float* __restrict__ be,
                            const float* __restrict__ gl, const float* __restrict__ bL,
                            const float* __restrict__ gr, const float* __restrict__ bR,
                            const float* __restrict__ Wo){
    __shared__ float redL[4], redR[4];
    int h = blockIdx.x, c = threadIdx.x;
    int lane = c & 31, warp = c >> 5;
    float wl = Wl[c*128 + h], wr = Wr[c*128 + h];
    g_WL[h*256 + c]       = __float2half_rn(gl[c] * wl);
    g_WL[h*256 + 128 + c] = __float2half_rn(We[c*128 + h]);
    g_WR[h*128 + c]       = __float2half_rn(gr[c] * wr);
    g_WG[h*128 + c]       = __float2half_rn(Wg[c*128 + h]);
    g_WoT[c*128 + h]      = __float2half_rn(Wo[h*128 + c]);
    float pl = bL[c] * wl, pr = bR[c] * wr;
    #pragma unroll
    for (int o = 16; o > 0; o >>= 1){
        pl += __shfl_xor_sync(~0u, pl, o);
        pr += __shfl_xor_sync(~0u, pr, o);
    }
    if (lane == 0){ redL[warp] = pl; redR[warp] = pr; }
    __syncthreads();
    if (c == 0){
        g_bL[h] = bl[h] + be[h] + redL[0]+redL[1]+redL[2]+redL[3];
        g_bR[h] = br[h] + redR[0]+redR[1]+redR[2]+redR[3];
        g_bG[h] = bg[h];
    }
}

// ---------------- kernel 1: 3-stage pipeline, ldmatrix fragments ----------------
#define K1_SMEM (64*264*2 + 3*128*72*2)

__device__ __forceinline__ void gemm16(const __half* __restrict__ Wsrc, int rsW, int nch, int aoff,
                                       __half* __restrict__ Bs, uint32_t bsb, uint32_t ahb,
                                       float (&acc)[2][4][4],
                                       int t, int wm, int wn, int lane){
    auto fill = [&](int buf, int kk){
        __half* Bp = Bs + buf*128*72;
        #pragma unroll
        for (int p = 0; p < 4; p++){
            int idx = t + p*256;
            int r = idx >> 3, q = idx & 7;
            cp16h(&Bp[r*72 + q*8], &Wsrc[(size_t)r*rsW + kk + q*8]);
        }
        cp_commit();
    };
    fill(0, 0);
    if (nch > 1) fill(1, 64);
    int aRow = lane & 15, aKq = (lane >> 4) << 3;
    int bN = lane & 7,  bKq = lane & 8;
    for (int c = 0; c < nch; c++){
        if (c + 1 < nch) cp_wait1(); else cp_wait0();
        __syncthreads();
        if (c + 2 < nch) fill((c + 2) % 3, (c + 2)*64);
        uint32_t Bb = bsb + (uint32_t)((c % 3)*128*72*2);
        int kk = aoff + c*64;
        #pragma unroll
        for (int ks = 0; ks < 4; ks++){
            int k0 = ks*16;
            uint32_t a[2][4], b[4][2];
            #pragma unroll
            for (int mm = 0; mm < 2; mm++){
                uint32_t sa = ahb + (uint32_t)(((wm*32 + mm*16 + aRow)*264 + kk + k0 + aKq)*2);
                ldm_x4(a[mm][0], a[mm][1], a[mm][2], a[mm][3], sa);
            }
            #pragma unroll
            for (int nn = 0; nn < 4; nn++){
                // FIX: buffer holds its chunk at local offset 0 (no c*64)
                uint32_t sb = Bb + (uint32_t)(((wn*32 + nn*8 + bN)*72 + k0 + bKq)*2);
                ldm_x2(b[nn][0], b[nn][1], sb);
            }
            #pragma unroll
            for (int mm = 0; mm < 2; mm++)
                #pragma unroll
                for (int nn = 0; nn < 4; nn++)
                    mma16(acc[mm][nn], a[mm][0],a[mm][1],a[mm][2],a[mm][3],
                          b[nn][0], b[nn][1]);
        }
    }
    __syncthreads();
}

template<int MODE>
__device__ __forceinline__ void store_out(float (&acc)[2][4][4], const float* __restrict__ bias,
                                          __half* __restrict__ stg, __half* __restrict__ dst,
                                          int r0, int t, int wm, int wn, int gq, int tg){
    #pragma unroll
    for (int mm = 0; mm < 2; mm++) for (int nn = 0; nn < 4; nn++){
        int row = wm*32 + mm*16 + gq, col = wn*32 + nn*8 + 2*tg;
        float b0 = bias[col], b1 = bias[col+1];
        float v0 = acc[mm][nn][0] + b0, v1 = acc[mm][nn][1] + b1;
        float v2 = acc[mm][nn][2] + b0, v3 = acc[mm][nn][3] + b1;
        if (MODE == 1){
            v0 = 1.f/(1.f + expf(-v0)); v1 = 1.f/(1.f + expf(-v1));
            v2 = 1.f/(1.f + expf(-v2)); v3 = 1.f/(1.f + expf(-v3));
        }
        stg[col*72 + row]           = __float2half_rn(v0);
        stg[(col+1)*72 + row]       = __float2half_rn(v1);
        stg[col*72 + row + 8]       = __float2half_rn(v2);
        stg[(col+1)*72 + row + 8]   = __float2half_rn(v3);
    }
    __syncthreads();
    #pragma unroll
    for (int p = 0; p < 4; p++){
        int idx = t + p*256;
        int col = idx >> 3, m8 = idx & 7;
        *(uint4*)&dst[(size_t)col*MM + r0 + m8*8] = *(const uint4*)&stg[col*72 + m8*8];
    }
    __syncthreads();
}

__global__ __launch_bounds__(256)
void k1_proj(const float* __restrict__ pair){
    extern __shared__ char smc[];
    __half* A_h  = (__half*)smc;
    float*  xs32 = (float*)(smc + 64*264*2);
    __half* Bs   = (__half*)(smc + 64*264*2);

    int t = threadIdx.x;
    int r0 = blockIdx.x * 64;
    int lane = t & 31, warp = t >> 5;
    int gq = lane >> 2, tg = lane & 3;
    int wm = warp >> 2, wn = warp & 3;
    uint32_t ahb = (uint32_t)__cvta_generic_to_shared(A_h);
    uint32_t bsb = (uint32_t)__cvta_generic_to_shared(Bs);

    #pragma unroll
    for (int p = 0; p < 8; p++){
        int idx = t + p*256;
        int c4 = idx & 31, m = idx >> 5;
        cp16f(&xs32[m*132 + c4*4], &pair[(size_t)(r0 + m)*128 + c4*4]);
    }
    cp_commit(); cp_wait0();
    __syncthreads();

    for (int rr = 0; rr < 8; rr++){
        int m = warp*8 + rr;
        float s = 0.f, ss = 0.f;
        #pragma unroll
        for (int q = 0; q < 4; q++){ float v = xs32[m*132 + lane + q*32]; s += v; ss += v*v; }
        #pragma unroll
        for (int o = 16; o > 0; o >>= 1){ s += __shfl_xor_sync(~0u, s, o); ss += __shfl_xor_sync(~0u, ss, o); }
        float mean = s * (1.f/128.f);
        float var  = ss * (1.f/128.f) - mean*mean;
        float inv  = rsqrtf(var + 1e-5f);
        #pragma unroll
        for (int q = 0; q < 4; q++){
            int c = lane + q*32;
            float v = xs32[m*132 + c];
            A_h[m*264 + c]       = __float2half_rn((v - mean) * inv);
            A_h[m*264 + 128 + c] = __float2half_rn(v);
        }
    }
    __syncthreads();

    float acc[2][4][4];

    #pragma unroll
    for (int a=0;a<2;a++) for (int b=0;b<4;b++) for (int c=0;c<4;c++) acc[a][b][c]=0.f;
    gemm16(g_WL, 256, 4, 0, Bs, bsb, ahb, acc, t, wm, wn, lane);
    store_out<0>(acc, g_bL, Bs, g_left, r0, t, wm, wn, gq, tg);

    #pragma unroll
    for (int a=0;a<2;a++) for (int b=0;b<4;b++) for (int c=0;c<4;c++) acc[a][b][c]=0.f;
    gemm16(g_WR, 128, 2, 0, Bs, bsb, ahb, acc, t, wm, wn, lane);
    store_out<0>(acc, g_bR, Bs, g_right, r0, t, wm, wn, gq, tg);

    #pragma unroll
    for (int a=0;a<2;a++) for (int b=0;b<4;b++) for (int c=0;c<4;c++) acc[a][b][c]=0.f;
    gemm16(g_WG, 128, 2, 128, Bs, bsb, ahb, acc, t, wm, wn, lane);
    store_out<1>(acc, g_bG, Bs, g_gate, r0, t, wm, wn, gq, tg);
}

// ---------------- kernel 2: 3-stage pipeline ----------------
#define K2_STG 35840
#define K2_SMEM (3*K2_STG)

__global__ __launch_bounds__(256)
void k2_tri(){
    extern __shared__ char smc[];
    __half* stg = (__half*)smc;

    int t = threadIdx.x;
    int lane = t & 31, warp = t >> 5;
    int gq = lane >> 2, tg = lane & 3;
    int wm = warp >> 2, wn = warp & 3;

    int h = blockIdx.z, i0 = blockIdx.y*128, j0 = blockIdx.x*128;
    const __half* L = g_left  + (size_t)h*MM;
    const __half* R = g_right + (size_t)h*MM;

    uint32_t base = (uint32_t)__cvta_generic_to_shared(smc);

    float acc[4][4][4];
    #pragma unroll
    for (int a=0;a<4;a++) for (int b=0;b<4;b++) for (int c=0;c<4;c++) acc[a][b][c]=0.f;

    auto fill = [&](int buf, int kk){
        __half* Ab = (__half*)(smc + buf*K2_STG);
        __half* Bb = (__half*)(smc + buf*K2_STG + 18432);
        #pragma unroll
        for (int p = 0; p < 4; p++){
            int idx = t + p*256;
            int r = idx >> 3, q = idx & 7;
            cp16h(&Ab[r*72 + q*8], &L[(size_t)(i0 + r)*384 + kk + q*8]);
        }
        #pragma unroll
        for (int p = 0; p < 4; p++){
            int idx = t + p*256;
            int kr = idx >> 4, q = idx & 15;
            cp16h(&Bb[kr*136 + q*8], &R[(size_t)(kk + kr)*384 + j0 + q*8]);
        }
        cp_commit();
    };

    fill(0, 0);
    fill(1, 64);

    int aRow = lane & 15, aKq = (lane >> 4) << 3;
    int bK   = lane & 15;

    for (int c = 0; c < 6; c++){
        if (c < 5) cp_wait1(); else cp_wait0();
        __syncthreads();
        if (c + 2 < 6) fill((c + 2) % 3, (c + 2)*64);
        uint32_t Ab_s = base + (uint32_t)((c % 3)*K2_STG);
        uint32_t Bb_s = Ab_s + 18432u;
        #pragma unroll
        for (int ks = 0; ks < 4; ks++){
            int k0 = ks*16;
            uint32_t a[4][4], b[4][2];
            #pragma unroll
            for (int mm = 0; mm < 4; mm++){
                uint32_t sa = Ab_s + (uint32_t)(((wm*64 + mm*16 + aRow)*72 + k0 + aKq)*2);
                ldm_x4(a[mm][0], a[mm][1], a[mm][2], a[mm][3], sa);
            }
            #pragma unroll
            for (int nn = 0; nn < 4; nn++){
                uint32_t sb = Bb_s + (uint32_t)(((k0 + bK)*136 + wn*32 + nn*8)*2);
                ldm_x2t(b[nn][0], b[nn][1], sb);
            }
            #pragma unroll
            for (int mm = 0; mm < 4; mm++)
                #pragma unroll
                for (int nn = 0; nn < 4; nn++)
                    mma16(acc[mm][nn], a[mm][0],a[mm][1],a[mm][2],a[mm][3],
                          b[nn][0], b[nn][1]);
        }
    }
    __syncthreads();

    #pragma unroll
    for (int mm = 0; mm < 4; mm++) for (int nn = 0; nn < 4; nn++){
        int row = wm*64 + mm*16 + gq;
        int col = wn*32 + nn*8 + 2*tg;
        stg[row*144 + col]         = __float2half_rn(acc[mm][nn][0]);
        stg[row*144 + col + 1]     = __float2half_rn(acc[mm][nn][1]);
        stg[(row+8)*144 + col]     = __float2half_rn(acc[mm][nn][2]);
        stg[(row+8)*144 + col + 1] = __float2half_rn(acc[mm][nn][3]);
    }
    __syncthreads();

    __half* G = g_gate + (size_t)h*MM;
    #pragma unroll
    for (int p = 0; p < 8; p++){
        int idx = t + p*256;
        int row = idx >> 4, c8 = idx & 15;
        __half* gp = &G[(size_t)(i0 + row)*384 + j0 + c8*8];
        uint4 sv = *(const uint4*)&stg[row*144 + c8*8];
        uint4 gv = *(const uint4*)gp;
        const __half2* s2 = (const __half2*)&sv;
        const __half2* g2 = (const __half2*)&gv;
        uint4 ov;
        __half2* o2 = (__half2*)&ov;
        #pragma unroll
        for (int q = 0; q < 4; q++){
            float2 sf = __half22float2(s2[q]);
            float2 gf = __half22float2(g2[q]);
            o2[q] = __floats2half2_rn(sf.x * gf.x, sf.y * gf.y);
        }
        *(uint4*)gp = ov;
    }
}

// ---------------- kernel 3: 3-stage pipeline ----------------
#define K3_SMEM (13824 + 3*10240 + 512)

__global__ __launch_bounds__(256)
void k3_out(const float* __restrict__ pair,
            const float* __restrict__ bo,   const float* __restrict__ gout,
            const float* __restrict__ bout, float* __restrict__ out){
    extern __shared__ char smc[];
    float* stage = (float*)smc;

    int t = threadIdx.x;
    int r0b = blockIdx.x * 64;
    int lane = t & 31, warp = t >> 5;
    int gq = lane >> 2, tg = lane & 3;
    int wm = warp >> 2, wn = warp & 3;
    const __half* O = g_gate;
    uint32_t base = (uint32_t)__cvta_generic_to_shared(smc);

    float acc[2][4][4];
    #pragma unroll
    for (int a=0;a<2;a++) for (int b=0;b<4;b++) for (int c=0;c<4;c++) acc[a][b][c]=0.f;

    auto fill = [&](int buf, int kk){
        __half* Ab = (__half*)(smc + buf*4608);
        __half* Bb = (__half*)(smc + 13824 + buf*10240);
        {
            int kl = t >> 3, m8 = t & 7;
            cp16h(&Ab[kl*72 + m8*8], &O[(size_t)(kk + kl)*MM + r0b + m8*8]);
        }
        #pragma unroll
        for (int p = 0; p < 2; p++){
            int idx = t + p*256;
            int n = idx >> 2, q = idx & 3;
            cp16h(&Bb[n*40 + q*8], &g_WoT[(size_t)n*128 + kk + q*8]);
        }
        cp_commit();
    };

    fill(0, 0);
    fill(1, 32);

    int quad = lane >> 3, qi = lane & 7;
    int aK = ((quad >> 1) << 3) + qi;
    int aM = (quad & 1) << 3;
    int bN = lane & 7, bKq = lane & 8;

    for (int c = 0; c < 4; c++){
        if (c < 3) cp_wait1(); else cp_wait0();
        __syncthreads();
        if (c + 2 < 4) fill((c + 2) % 3, (c + 2)*32);
        uint32_t Ab_s = base + (uint32_t)((c % 3)*4608);
        uint32_t Bb_s = base + 13824u + (uint32_t)((c % 3)*10240);
        #pragma unroll
        for (int ks = 0; ks < 2; ks++){
            int k0 = ks*16;
            uint32_t a[2][4], b[4][2];
            #pragma unroll
            for (int mm = 0; mm < 2; mm++){
                uint32_t sa = Ab_s + (uint32_t)(((k0 + aK)*72 + wm*32 + mm*16 + aM)*2);
                ldm_x4t(a[mm][0], a[mm][1], a[mm][2], a[mm][3], sa);
            }
            #pragma unroll
            for (int nn = 0; nn < 4; nn++){
                uint32_t sb = Bb_s + (uint32_t)(((wn*32 + nn*8 + bN)*40 + k0 + bKq)*2);
                ldm_x2(b[nn][0], b[nn][1], sb);
            }
            #pragma unroll
            for (int mm = 0; mm < 2; mm++)
                #pragma unroll
                for (int nn = 0; nn < 4; nn++)
                    mma16(acc[mm][nn], a[mm][0],a[mm][1],a[mm][2],a[mm][3],
                          b[nn][0], b[nn][1]);
        }
    }
    __syncthreads();

    #pragma unroll
    for (int mm = 0; mm < 2; mm++) for (int nn = 0; nn < 4; nn++){
        int row = wm*32 + mm*16 + gq, col = wn*32 + nn*8 + 2*tg;
        const float* pp = &pair[(size_t)(r0b + row)*128 + col];
        stage[row*133 + col]         = acc[mm][nn][0] + bo[col]   + pp[0];
        stage[row*133 + col + 1]     = acc[mm][nn][1] + bo[col+1] + pp[1];
        stage[(row+8)*133 + col]     = acc[mm][nn][2] + bo[col]   + pp[128*8];
        stage[(row+8)*133 + col + 1] = acc[mm][nn][3] + bo[col+1] + pp[128*8 + 1];
    }
    __syncthreads();

    for (int rr = 0; rr < 8; rr++){
        int m = warp*8 + rr;
        float s = 0.f, ss = 0.f;
        #pragma unroll
        for (int q = 0; q < 4; q++){ float v = stage[m*133 + lane + q*32]; s += v; ss += v*v; }
        #pragma unroll
        for (int o = 16; o > 0; o >>= 1){ s += __shfl_xor_sync(~0u, s, o); ss += __shfl_xor_sync(~0u, ss, o); }
        float mean = s * (1.f/128.f);
        float var  = ss * (1.f/128.f) - mean*mean;
        float inv  = rsqrtf(var + 1e-5f);
        #pragma unroll
        for (int q = 0; q < 4; q++){
            int c = lane + q*32;
            out[(size_t)(r0b + m)*128 + c] = (stage[m*133 + c] - mean) * inv * gout[c] + bout[c];
        }
    }
}

// ---------------- launch ----------------
extern "C" void kernel_launch(void* const* d_in, const int* in_sizes, int n_in,
                              void* d_out, int out_size){
    const float* pair   = (const float*)d_in[0];
    const float* g_l    = (const float*)d_in[1];
    const float* b_l    = (const float*)d_in[2];
    const float* g_r    = (const float*)d_in[3];
    const float* b_r    = (const float*)d_in[4];
    const float* g_o    = (const float*)d_in[5];
    const float* b_o    = (const float*)d_in[6];
    const float* W_l    = (const float*)d_in[7];
    const float* bias_l = (const float*)d_in[8];
    const float* W_r    = (const float*)d_in[9];
    const float* bias_r = (const float*)d_in[10];
    const float* W_g    = (const float*)d_in[11];
    const float* bias_g = (const float*)d_in[12];
    const float* W_e    = (const float*)d_in[13];
    const float* bias_e = (const float*)d_in[14];
    const float* W_o    = (const float*)d_in[15];
    const float* bias_o = (const float*)d_in[16];
    float* out = (float*)d_out;

    cudaFuncSetAttribute(k1_proj, cudaFuncAttributeMaxDynamicSharedMemorySize, K1_SMEM);
    cudaFuncSetAttribute(k2_tri,  cudaFuncAttributeMaxDynamicSharedMemorySize, K2_SMEM);
    cudaFuncSetAttribute(k3_out,  cudaFuncAttributeMaxDynamicSharedMemorySize, K3_SMEM);

    prep_kernel<<<128, 128>>>(W_l, bias_l, W_r, bias_r, W_g, bias_g, W_e, bias_e,
                              g_l, b_l, g_r, b_r, W_o);
    k1_proj<<<MM/64, 256, K1_SMEM>>>(pair);
    k2_tri<<<dim3(3, 3, 128), 256, K2_SMEM>>>();
    k3_out<<<MM/64, 256, K3_SMEM>>>(pair, bias_o, g_o, b_o, out);
}

// round 14
// speedup vs baseline: 1.0437x; 1.0437x over previous
#include <cuda_runtime.h>
#include <cuda_fp16.h>
#include <cstdint>

#define CC 128
#define HH 128
#define MM (384*384)

__device__ __align__(16) __half g_left [(size_t)HH*MM];   // [h][i*384+k]
__device__ __align__(16) __half g_right[(size_t)HH*MM];   // [h][k*384+j]
__device__ __align__(16) __half g_gate [(size_t)HH*MM];   // [h][i*384+j]; k2 overwrites in-place
__device__ __align__(16) __half g_WL [128*256];
__device__ __align__(16) __half g_WR [128*128];
__device__ __align__(16) __half g_WG [128*128];
__device__ __align__(16) __half g_WoT[128*128];
__device__ float g_bL[128], g_bR[128], g_bG[128];

__device__ __forceinline__ void mma16(float* d, uint32_t a0,uint32_t a1,uint32_t a2,uint32_t a3,
                                      uint32_t b0,uint32_t b1){
    asm volatile(
      "mma.sync.aligned.m16n8k16.row.col.f32.f16.f16.f32 "
      "{%0,%1,%2,%3},{%4,%5,%6,%7},{%8,%9},{%0,%1,%2,%3};\n"
      : "+f"(d[0]),"+f"(d[1]),"+f"(d[2]),"+f"(d[3])
      : "r"(a0),"r"(a1),"r"(a2),"r"(a3),"r"(b0),"r"(b1));
}
__device__ __forceinline__ void cp16h(__half* s, const __half* g){
    unsigned sa = (unsigned)__cvta_generic_to_shared(s);
    asm volatile("cp.async.ca.shared.global [%0], [%1], 16;" :: "r"(sa), "l"(g) : "memory");
}
__device__ __forceinline__ void cp16f(float* s, const float* g){
    unsigned sa = (unsigned)__cvta_generic_to_shared(s);
    asm volatile("cp.async.ca.shared.global [%0], [%1], 16;" :: "r"(sa), "l"(g) : "memory");
}
__device__ __forceinline__ void cp_commit(){ asm volatile("cp.async.commit_group;" ::: "memory"); }
__device__ __forceinline__ void cp_wait1(){ asm volatile("cp.async.wait_group 1;" ::: "memory"); }
__device__ __forceinline__ void cp_wait0(){ asm volatile("cp.async.wait_group 0;" ::: "memory"); }
__device__ __forceinline__ uint32_t ldu32(const __half* p){ return *(const uint32_t*)p; }
__device__ __forceinline__ void ldm_x4(uint32_t& r0, uint32_t& r1, uint32_t& r2, uint32_t& r3, uint32_t sa){
    asm volatile("ldmatrix.sync.aligned.m8n8.x4.shared.b16 {%0,%1,%2,%3}, [%4];"
                 : "=r"(r0),"=r"(r1),"=r"(r2),"=r"(r3) : "r"(sa));
}
__device__ __forceinline__ void ldm_x4t(uint32_t& r0, uint32_t& r1, uint32_t& r2, uint32_t& r3, uint32_t sa){
    asm volatile("ldmatrix.sync.aligned.m8n8.x4.trans.shared.b16 {%0,%1,%2,%3}, [%4];"
                 : "=r"(r0),"=r"(r1),"=r"(r2),"=r"(r3) : "r"(sa));
}
__device__ __forceinline__ void ldm_x2t(uint32_t& r0, uint32_t& r1, uint32_t sa){
    asm volatile("ldmatrix.sync.aligned.m8n8.x2.trans.shared.b16 {%0,%1}, [%2];"
                 : "=r"(r0),"=r"(r1) : "r"(sa));
}

// ---------------- prep ----------------
__global__ void prep_kernel(const float* __restrict__ Wl, const float* __restrict__ bl,
                            const float* __restrict__ Wr, const float* __restrict__ br,
                            const float* __restrict__ Wg, const float* __restrict__ bg,
                            const float* __restrict__ We, const float* __restrict__ be,
                            const float* __restrict__ gl, const float* __restrict__ bL,
                            const float* __restrict__ gr, const float* __restrict__ bR,
                            const float* __restrict__ Wo){
    __shared__ float redL[4], redR[4];
    int h = blockIdx.x, c = threadIdx.x;
    int lane = c & 31, warp = c >> 5;
    float wl = Wl[c*128 + h], wr = Wr[c*128 + h];
    g_WL[h*256 + c]       = __float2half_rn(gl[c] * wl);
    g_WL[h*256 + 128 + c] = __float2half_rn(We[c*128 + h]);
    g_WR[h*128 + c]       = __float2half_rn(gr[c] * wr);
    g_WG[h*128 + c]       = __float2half_rn(Wg[c*128 + h]);
    g_WoT[c*128 + h]      = __float2half_rn(Wo[h*128 + c]);
    float pl = bL[c] * wl, pr = bR[c] * wr;
    #pragma unroll
    for (int o = 16; o > 0; o >>= 1){
        pl += __shfl_xor_sync(~0u, pl, o);
        pr += __shfl_xor_sync(~0u, pr, o);
    }
    if (lane == 0){ redL[warp] = pl; redR[warp] = pr; }
    __syncthreads();
    if (c == 0){
        g_bL[h] = bl[h] + be[h] + redL[0]+redL[1]+redL[2]+redL[3];
        g_bR[h] = br[h] + redR[0]+redR[1]+redR[2]+redR[3];
        g_bG[h] = bg[h];
    }
}

// ---------------- kernel 1 (round-11 verbatim) ----------------
#define K1_SMEM (64*264*2 + 2*128*72*2)

__device__ __forceinline__ void gemm16(const __half* __restrict__ Wsrc, int rsW, int nch, int aoff,
                                       __half* __restrict__ Bs, const __half* __restrict__ A_h,
                                       float (&acc)[2][4][4],
                                       int t, int wm, int wn, int gq, int tg){
    auto fill = [&](int s, int kk){
        #pragma unroll
        for (int p = 0; p < 4; p++){
            int idx = t + p*256;
            int r = idx >> 3, q = idx & 7;
            cp16h(&Bs[s*128*72 + r*72 + q*8], &Wsrc[(size_t)r*rsW + kk + q*8]);
        }
        cp_commit();
    };
    fill(0, 0);
    if (nch > 1) fill(1, 64);
    for (int c = 0; c < nch; c++){
        int s = c & 1;
        if (c + 1 < nch) cp_wait1(); else cp_wait0();
        __syncthreads();
        const __half* Bb = &Bs[s*128*72];
        int kk = c*64;
        #pragma unroll
        for (int ks = 0; ks < 4; ks++){
            uint32_t a[2][4];
            #pragma unroll
            for (int mm = 0; mm < 2; mm++){
                const __half* ap = &A_h[(wm*32 + mm*16 + gq)*264 + aoff + kk + ks*16 + 2*tg];
                a[mm][0] = ldu32(ap);        a[mm][1] = ldu32(ap + 8*264);
                a[mm][2] = ldu32(ap + 8);    a[mm][3] = ldu32(ap + 8*264 + 8);
            }
            #pragma unroll
            for (int nn = 0; nn < 4; nn++){
                const __half* bp = &Bb[(wn*32 + nn*8 + gq)*72 + ks*16 + 2*tg];
                uint32_t b0 = ldu32(bp), b1 = ldu32(bp + 8);
                #pragma unroll
                for (int mm = 0; mm < 2; mm++)
                    mma16(acc[mm][nn], a[mm][0],a[mm][1],a[mm][2],a[mm][3], b0, b1);
            }
        }
        __syncthreads();
        if (c + 2 < nch) fill(s, (c + 2)*64);
    }
}

template<int MODE>
__device__ __forceinline__ void store_out(float (&acc)[2][4][4], const float* __restrict__ bias,
                                          __half* __restrict__ stg, __half* __restrict__ dst,
                                          int r0, int t, int wm, int wn, int gq, int tg){
    #pragma unroll
    for (int mm = 0; mm < 2; mm++) for (int nn = 0; nn < 4; nn++){
        int row = wm*32 + mm*16 + gq, col = wn*32 + nn*8 + 2*tg;
        float b0 = bias[col], b1 = bias[col+1];
        float v0 = acc[mm][nn][0] + b0, v1 = acc[mm][nn][1] + b1;
        float v2 = acc[mm][nn][2] + b0, v3 = acc[mm][nn][3] + b1;
        if (MODE == 1){
            v0 = 1.f/(1.f + expf(-v0)); v1 = 1.f/(1.f + expf(-v1));
            v2 = 1.f/(1.f + expf(-v2)); v3 = 1.f/(1.f + expf(-v3));
        }
        stg[col*72 + row]           = __float2half_rn(v0);
        stg[(col+1)*72 + row]       = __float2half_rn(v1);
        stg[col*72 + row + 8]       = __float2half_rn(v2);
        stg[(col+1)*72 + row + 8]   = __float2half_rn(v3);
    }
    __syncthreads();
    #pragma unroll
    for (int p = 0; p < 4; p++){
        int idx = t + p*256;
        int col = idx >> 3, m8 = idx & 7;
        *(uint4*)&dst[(size_t)col*MM + r0 + m8*8] = *(const uint4*)&stg[col*72 + m8*8];
    }
    __syncthreads();
}

__global__ __launch_bounds__(256)
void k1_proj(const float* __restrict__ pair){
    extern __shared__ char smc[];
    __half* A_h  = (__half*)smc;
    float*  xs32 = (float*)(smc + 64*264*2);
    __half* Bs   = (__half*)(smc + 64*264*2);

    int t = threadIdx.x;
    int r0 = blockIdx.x * 64;
    int lane = t & 31, warp = t >> 5;
    int gq = lane >> 2, tg = lane & 3;
    int wm = warp >> 2, wn = warp & 3;

    #pragma unroll
    for (int p = 0; p < 8; p++){
        int idx = t + p*256;
        int c4 = idx & 31, m = idx >> 5;
        cp16f(&xs32[m*132 + c4*4], &pair[(size_t)(r0 + m)*128 + c4*4]);
    }
    cp_commit(); cp_wait0();
    __syncthreads();

    for (int rr = 0; rr < 8; rr++){
        int m = warp*8 + rr;
        float s = 0.f, ss = 0.f;
        #pragma unroll
        for (int q = 0; q < 4; q++){ float v = xs32[m*132 + lane + q*32]; s += v; ss += v*v; }
        #pragma unroll
        for (int o = 16; o > 0; o >>= 1){ s += __shfl_xor_sync(~0u, s, o); ss += __shfl_xor_sync(~0u, ss, o); }
        float mean = s * (1.f/128.f);
        float var  = ss * (1.f/128.f) - mean*mean;
        float inv  = rsqrtf(var + 1e-5f);
        #pragma unroll
        for (int q = 0; q < 4; q++){
            int c = lane + q*32;
            float v = xs32[m*132 + c];
            A_h[m*264 + c]       = __float2half_rn((v - mean) * inv);
            A_h[m*264 + 128 + c] = __float2half_rn(v);
        }
    }
    __syncthreads();

    float acc[2][4][4];

    #pragma unroll
    for (int a=0;a<2;a++) for (int b=0;b<4;b++) for (int c=0;c<4;c++) acc[a][b][c]=0.f;
    gemm16(g_WL, 256, 4, 0, Bs, A_h, acc, t, wm, wn, gq, tg);
    store_out<0>(acc, g_bL, Bs, g_left, r0, t, wm, wn, gq, tg);

    #pragma unroll
    for (int a=0;a<2;a++) for (int b=0;b<4;b++) for (int c=0;c<4;c++) acc[a][b][c]=0.f;
    gemm16(g_WR, 128, 2, 0, Bs, A_h, acc, t, wm, wn, gq, tg);
    store_out<0>(acc, g_bR, Bs, g_right, r0, t, wm, wn, gq, tg);

    #pragma unroll
    for (int a=0;a<2;a++) for (int b=0;b<4;b++) for (int c=0;c<4;c++) acc[a][b][c]=0.f;
    gemm16(g_WG, 128, 2, 128, Bs, A_h, acc, t, wm, wn, gq, tg);
    store_out<1>(acc, g_bG, Bs, g_gate, r0, t, wm, wn, gq, tg);
}

// ---------------- kernel 2 (round-11 verbatim) ----------------
#define K2_SMEM (2*128*72*2 + 2*64*136*2)

__global__ __launch_bounds__(256)
void k2_tri(){
    extern __shared__ char smc[];
    __half* As = (__half*)smc;                    // 2 * 128*72
    __half* Bs = (__half*)(smc + 2*128*72*2);     // 2 * 64*136
    __half* stg = (__half*)smc;                   // reused: 128*144

    int t = threadIdx.x;
    int lane = t & 31, warp = t >> 5;
    int gq = lane >> 2, tg = lane & 3;
    int wm = warp >> 2, wn = warp & 3;

    int h = blockIdx.z, i0 = blockIdx.y*128, j0 = blockIdx.x*128;
    const __half* L = g_left  + (size_t)h*MM;
    const __half* R = g_right + (size_t)h*MM;

    uint32_t as_base = (uint32_t)__cvta_generic_to_shared(As);
    uint32_t bs_base = (uint32_t)__cvta_generic_to_shared(Bs);

    float acc[4][4][4];
    #pragma unroll
    for (int a=0;a<4;a++) for (int b=0;b<4;b++) for (int c=0;c<4;c++) acc[a][b][c]=0.f;

    auto fill = [&](int s, int kk){
        #pragma unroll
        for (int p = 0; p < 4; p++){
            int idx = t + p*256;
            int r = idx >> 3, q = idx & 7;
            cp16h(&As[s*128*72 + r*72 + q*8], &L[(size_t)(i0 + r)*384 + kk + q*8]);
        }
        #pragma unroll
        for (int p = 0; p < 4; p++){
            int idx = t + p*256;
            int kr = idx >> 4, q = idx & 15;
            cp16h(&Bs[s*64*136 + kr*136 + q*8], &R[(size_t)(kk + kr)*384 + j0 + q*8]);
        }
        cp_commit();
    };

    fill(0, 0);
    fill(1, 64);

    int aRow = lane & 15, aKq = (lane >> 4) << 3;
    int bK   = lane & 15;

    for (int c = 0; c < 6; c++){
        int s = c & 1;
        if (c < 5) cp_wait1(); else cp_wait0();
        __syncthreads();
        uint32_t Ab_s = as_base + (uint32_t)(s*128*72*2);
        uint32_t Bb_s = bs_base + (uint32_t)(s*64*136*2);
        #pragma unroll
        for (int ks = 0; ks < 4; ks++){
            int k0 = ks*16;
            uint32_t a[4][4], b[4][2];
            #pragma unroll
            for (int mm = 0; mm < 4; mm++){
                uint32_t sa = Ab_s + (uint32_t)(((wm*64 + mm*16 + aRow)*72 + k0 + aKq)*2);
                ldm_x4(a[mm][0], a[mm][1], a[mm][2], a[mm][3], sa);
            }
            #pragma unroll
            for (int nn = 0; nn < 4; nn++){
                uint32_t sb = Bb_s + (uint32_t)(((k0 + bK)*136 + wn*32 + nn*8)*2);
                ldm_x2t(b[nn][0], b[nn][1], sb);
            }
            #pragma unroll
            for (int mm = 0; mm < 4; mm++)
                #pragma unroll
                for (int nn = 0; nn < 4; nn++)
                    mma16(acc[mm][nn], a[mm][0],a[mm][1],a[mm][2],a[mm][3],
                          b[nn][0], b[nn][1]);
        }
        __syncthreads();
        if (c + 2 < 6) fill(s, (c + 2)*64);
    }

    #pragma unroll
    for (int mm = 0; mm < 4; mm++) for (int nn = 0; nn < 4; nn++){
        int row = wm*64 + mm*16 + gq;
        int col = wn*32 + nn*8 + 2*tg;
        stg[row*144 + col]         = __float2half_rn(acc[mm][nn][0]);
        stg[row*144 + col + 1]     = __float2half_rn(acc[mm][nn][1]);
        stg[(row+8)*144 + col]     = __float2half_rn(acc[mm][nn][2]);
        stg[(row+8)*144 + col + 1] = __float2half_rn(acc[mm][nn][3]);
    }
    __syncthreads();

    __half* G = g_gate + (size_t)h*MM;
    #pragma unroll
    for (int p = 0; p < 8; p++){
        int idx = t + p*256;
        int row = idx >> 4, c8 = idx & 15;
        __half* gp = &G[(size_t)(i0 + row)*384 + j0 + c8*8];
        uint4 sv = *(const uint4*)&stg[row*144 + c8*8];
        uint4 gv = *(const uint4*)gp;
        const __half2* s2 = (const __half2*)&sv;
        const __half2* g2 = (const __half2*)&gv;
        uint4 ov;
        __half2* o2 = (__half2*)&ov;
        #pragma unroll
        for (int q = 0; q < 4; q++){
            float2 sf = __half22float2(s2[q]);
            float2 gf = __half22float2(g2[q]);
            o2[q] = __floats2half2_rn(sf.x * gf.x, sf.y * gf.y);
        }
        *(uint4*)gp = ov;
    }
}

// ---------------- kernel 3: K-chunk 64, both chunks prefetched ----------------
// As[2]: 64k x 64m stride 72 -> 9216B each; Bs[2]: 128n x 64k stride 72 -> 18432B each
#define K3_SMEM (2*64*72*2 + 2*128*72*2)   // 18432 + 36864 = 55296; stage f32 64*133*4=34048 overlays

__global__ __launch_bounds__(256)
void k3_out(const float* __restrict__ pair,
            const float* __restrict__ bo,   const float* __restrict__ gout,
            const float* __restrict__ bout, float* __restrict__ out){
    extern __shared__ char smc[];
    __half* As = (__half*)smc;                    // 2 * 64*72
    __half* Bs = (__half*)(smc + 2*64*72*2);      // 2 * 128*72
    float* stage = (float*)smc;

    int t = threadIdx.x;
    int r0b = blockIdx.x * 64;
    int lane = t & 31, warp = t >> 5;
    int gq = lane >> 2, tg = lane & 3;
    int wm = warp >> 2, wn = warp & 3;
    const __half* O = g_gate;

    uint32_t as_base = (uint32_t)__cvta_generic_to_shared(As);

    float acc[2][4][4];
    #pragma unroll
    for (int a=0;a<2;a++) for (int b=0;b<4;b++) for (int c=0;c<4;c++) acc[a][b][c]=0.f;

    auto fill = [&](int s, int kk){
        #pragma unroll
        for (int p = 0; p < 2; p++){
            int idx = t + p*256;              // 0..511
            int kl = idx >> 3, m8 = idx & 7;  // kl 0..63
            cp16h(&As[s*64*72 + kl*72 + m8*8], &O[(size_t)(kk + kl)*MM + r0b + m8*8]);
        }
        #pragma unroll
        for (int p = 0; p < 4; p++){
            int idx = t + p*256;              // 0..1023
            int n = idx >> 3, q = idx & 7;    // n 0..127, q covers 64 k
            cp16h(&Bs[s*128*72 + n*72 + q*8], &g_WoT[(size_t)n*128 + kk + q*8]);
        }
        cp_commit();
    };

    fill(0, 0);
    fill(1, 64);

    int quad = lane >> 3, qi = lane & 7;
    int aK = ((quad >> 1) << 3) + qi;
    int aM = (quad & 1) << 3;

    for (int c = 0; c < 2; c++){
        if (c == 0) cp_wait1(); else cp_wait0();
        __syncthreads();
        uint32_t Ab_s = as_base + (uint32_t)(c*64*72*2);
        const __half* Bb = &Bs[c*128*72];
        #pragma unroll
        for (int ks = 0; ks < 4; ks++){
            int k0 = ks*16;
            uint32_t a[2][4], b[4][2];
            #pragma unroll
            for (int mm = 0; mm < 2; mm++){
                uint32_t sa = Ab_s + (uint32_t)(((k0 + aK)*72 + wm*32 + mm*16 + aM)*2);
                ldm_x4t(a[mm][0], a[mm][1], a[mm][2], a[mm][3], sa);
            }
            #pragma unroll
            for (int nn = 0; nn < 4; nn++){
                const __half* bp = &Bb[(wn*32 + nn*8 + gq)*72 + k0 + 2*tg];
                b[nn][0] = ldu32(bp);  b[nn][1] = ldu32(bp + 8);
            }
            #pragma unroll
            for (int mm = 0; mm < 2; mm++)
                #pragma unroll
                for (int nn = 0; nn < 4; nn++)
                    mma16(acc[mm][nn], a[mm][0],a[mm][1],a[mm][2],a[mm][3],
                          b[nn][0], b[nn][1]);
        }
    }
    __syncthreads();

    #pragma unroll
    for (int mm = 0; mm < 2; mm++) for (int nn = 0; nn < 4; nn++){
        int row = wm*32 + mm*16 + gq, col = wn*32 + nn*8 + 2*tg;
        const float* pp = &pair[(size_t)(r0b + row)*128 + col];
        stage[row*133 + col]         = acc[mm][nn][0] + bo[col]   + pp[0];
        stage[row*133 + col + 1]     = acc[mm][nn][1] + bo[col+1] + pp[1];
        stage[(row+8)*133 + col]     = acc[mm][nn][2] + bo[col]   + pp[128*8];
        stage[(row+8)*133 + col + 1] = acc[mm][nn][3] + bo[col+1] + pp[128*8 + 1];
    }
    __syncthreads();

    for (int rr = 0; rr < 8; rr++){
        int m = warp*8 + rr;
        float s = 0.f, ss = 0.f;
        #pragma unroll
        for (int q = 0; q < 4; q++){ float v = stage[m*133 + lane + q*32]; s += v; ss += v*v; }
        #pragma unroll
        for (int o = 16; o > 0; o >>= 1){ s += __shfl_xor_sync(~0u, s, o); ss += __shfl_xor_sync(~0u, ss, o); }
        float mean = s * (1.f/128.f);
        float var  = ss * (1.f/128.f) - mean*mean;
        float inv  = rsqrtf(var + 1e-5f);
        #pragma unroll
        for (int q = 0; q < 4; q++){
            int c = lane + q*32;
            out[(size_t)(r0b + m)*128 + c] = (stage[m*133 + c] - mean) * inv * gout[c] + bout[c];
        }
    }
}

// ---------------- launch ----------------
extern "C" void kernel_launch(void* const* d_in, const int* in_sizes, int n_in,
                              void* d_out, int out_size){
    const float* pair   = (const float*)d_in[0];
    const float* g_l    = (const float*)d_in[1];
    const float* b_l    = (const float*)d_in[2];
    const float* g_r    = (const float*)d_in[3];
    const float* b_r    = (const float*)d_in[4];
    const float* g_o    = (const float*)d_in[5];
    const float* b_o    = (const float*)d_in[6];
    const float* W_l    = (const float*)d_in[7];
    const float* bias_l = (const float*)d_in[8];
    const float* W_r    = (const float*)d_in[9];
    const float* bias_r = (const float*)d_in[10];
    const float* W_g    = (const float*)d_in[11];
    const float* bias_g = (const float*)d_in[12];
    const float* W_e    = (const float*)d_in[13];
    const float* bias_e = (const float*)d_in[14];
    const float* W_o    = (const float*)d_in[15];
    const float* bias_o = (const float*)d_in[16];
    float* out = (float*)d_out;

    cudaFuncSetAttribute(k1_proj, cudaFuncAttributeMaxDynamicSharedMemorySize, K1_SMEM);
    cudaFuncSetAttribute(k2_tri,  cudaFuncAttributeMaxDynamicSharedMemorySize, K2_SMEM);
    cudaFuncSetAttribute(k3_out,  cudaFuncAttributeMaxDynamicSharedMemorySize, K3_SMEM);

    prep_kernel<<<128, 128>>>(W_l, bias_l, W_r, bias_r, W_g, bias_g, W_e, bias_e,
                              g_l, b_l, g_r, b_r, W_o);
    k1_proj<<<MM/64, 256, K1_SMEM>>>(pair);
    k2_tri<<<dim3(3, 3, 128), 256, K2_SMEM>>>();
    k3_out<<<MM/64, 256, K3_SMEM>>>(pair, bias_o, g_o, b_o, out);
}

// round 15
// speedup vs baseline: 1.0830x; 1.0376x over previous
#include <cuda_runtime.h>
#include <cuda_fp16.h>
#include <cstdint>

#define CC 128
#define HH 128
#define MM (384*384)

__device__ __align__(16) __half g_left [(size_t)HH*MM];   // [h][i*384+k]
__device__ __align__(16) __half g_right[(size_t)HH*MM];   // [h][k*384+j]
__device__ __align__(16) __half g_gate [(size_t)HH*MM];   // [h][i*384+j]; k2 overwrites in-place
__device__ __align__(16) __half g_WL [128*256];
__device__ __align__(16) __half g_WR [128*128];
__device__ __align__(16) __half g_WG [128*128];
__device__ __align__(16) __half g_WoT[128*128];
__device__ float g_bL[128], g_bR[128], g_bG[128];

__device__ __forceinline__ void mma16(float* d, uint32_t a0,uint32_t a1,uint32_t a2,uint32_t a3,
                                      uint32_t b0,uint32_t b1){
    asm volatile(
      "mma.sync.aligned.m16n8k16.row.col.f32.f16.f16.f32 "
      "{%0,%1,%2,%3},{%4,%5,%6,%7},{%8,%9},{%0,%1,%2,%3};\n"
      : "+f"(d[0]),"+f"(d[1]),"+f"(d[2]),"+f"(d[3])
      : "r"(a0),"r"(a1),"r"(a2),"r"(a3),"r"(b0),"r"(b1));
}
__device__ __forceinline__ void cp16h(__half* s, const __half* g){
    unsigned sa = (unsigned)__cvta_generic_to_shared(s);
    asm volatile("cp.async.ca.shared.global [%0], [%1], 16;" :: "r"(sa), "l"(g) : "memory");
}
__device__ __forceinline__ void cp16hg(__half* s, const __half* g){   // L1-bypass (streaming)
    unsigned sa = (unsigned)__cvta_generic_to_shared(s);
    asm volatile("cp.async.cg.shared.global [%0], [%1], 16;" :: "r"(sa), "l"(g) : "memory");
}
__device__ __forceinline__ void cp16f(float* s, const float* g){
    unsigned sa = (unsigned)__cvta_generic_to_shared(s);
    asm volatile("cp.async.ca.shared.global [%0], [%1], 16;" :: "r"(sa), "l"(g) : "memory");
}
__device__ __forceinline__ void cp_commit(){ asm volatile("cp.async.commit_group;" ::: "memory"); }
__device__ __forceinline__ void cp_wait1(){ asm volatile("cp.async.wait_group 1;" ::: "memory"); }
__device__ __forceinline__ void cp_wait0(){ asm volatile("cp.async.wait_group 0;" ::: "memory"); }
__device__ __forceinline__ uint32_t ldu32(const __half* p){ return *(const uint32_t*)p; }
__device__ __forceinline__ void ldm_x4(uint32_t& r0, uint32_t& r1, uint32_t& r2, uint32_t& r3, uint32_t sa){
    asm volatile("ldmatrix.sync.aligned.m8n8.x4.shared.b16 {%0,%1,%2,%3}, [%4];"
                 : "=r"(r0),"=r"(r1),"=r"(r2),"=r"(r3) : "r"(sa));
}
__device__ __forceinline__ void ldm_x4t(uint32_t& r0, uint32_t& r1, uint32_t& r2, uint32_t& r3, uint32_t sa){
    asm volatile("ldmatrix.sync.aligned.m8n8.x4.trans.shared.b16 {%0,%1,%2,%3}, [%4];"
                 : "=r"(r0),"=r"(r1),"=r"(r2),"=r"(r3) : "r"(sa));
}
__device__ __forceinline__ void ldm_x2t(uint32_t& r0, uint32_t& r1, uint32_t sa){
    asm volatile("ldmatrix.sync.aligned.m8n8.x2.trans.shared.b16 {%0,%1}, [%2];"
                 : "=r"(r0),"=r"(r1) : "r"(sa));
}

// ---------------- prep ----------------
__global__ void prep_kernel(const float* __restrict__ Wl, const float* __restrict__ bl,
                            const float* __restrict__ Wr, const float* __restrict__ br,
                            const float* __restrict__ Wg, const float* __restrict__ bg,
                            const float* __restrict__ We, const float* __restrict__ be,
                            const float* __restrict__ gl, const float* __restrict__ bL,
                            const float* __restrict__ gr, const float* __restrict__ bR,
                            const float* __restrict__ Wo){
    __shared__ float redL[4], redR[4];
    int h = blockIdx.x, c = threadIdx.x;
    int lane = c & 31, warp = c >> 5;
    float wl = Wl[c*128 + h], wr = Wr[c*128 + h];
    g_WL[h*256 + c]       = __float2half_rn(gl[c] * wl);
    g_WL[h*256 + 128 + c] = __float2half_rn(We[c*128 + h]);
    g_WR[h*128 + c]       = __float2half_rn(gr[c] * wr);
    g_WG[h*128 + c]       = __float2half_rn(Wg[c*128 + h]);
    g_WoT[c*128 + h]      = __float2half_rn(Wo[h*128 + c]);
    float pl = bL[c] * wl, pr = bR[c] * wr;
    #pragma unroll
    for (int o = 16; o > 0; o >>= 1){
        pl += __shfl_xor_sync(~0u, pl, o);
        pr += __shfl_xor_sync(~0u, pr, o);
    }
    if (lane == 0){ redL[warp] = pl; redR[warp] = pr; }
    __syncthreads();
    if (c == 0){
        g_bL[h] = bl[h] + be[h] + redL[0]+redL[1]+redL[2]+redL[3];
        g_bR[h] = br[h] + redR[0]+redR[1]+redR[2]+redR[3];
        g_bG[h] = bg[h];
    }
}

// ---------------- kernel 1 (round-11) ----------------
#define K1_SMEM (64*264*2 + 2*128*72*2)

__device__ __forceinline__ void gemm16(const __half* __restrict__ Wsrc, int rsW, int nch, int aoff,
                                       __half* __restrict__ Bs, const __half* __restrict__ A_h,
                                       float (&acc)[2][4][4],
                                       int t, int wm, int wn, int gq, int tg){
    auto fill = [&](int s, int kk){
        #pragma unroll
        for (int p = 0; p < 4; p++){
            int idx = t + p*256;
            int r = idx >> 3, q = idx & 7;
            cp16h(&Bs[s*128*72 + r*72 + q*8], &Wsrc[(size_t)r*rsW + kk + q*8]);
        }
        cp_commit();
    };
    fill(0, 0);
    if (nch > 1) fill(1, 64);
    for (int c = 0; c < nch; c++){
        int s = c & 1;
        if (c + 1 < nch) cp_wait1(); else cp_wait0();
        __syncthreads();
        const __half* Bb = &Bs[s*128*72];
        int kk = c*64;
        #pragma unroll
        for (int ks = 0; ks < 4; ks++){
            uint32_t a[2][4];
            #pragma unroll
            for (int mm = 0; mm < 2; mm++){
                const __half* ap = &A_h[(wm*32 + mm*16 + gq)*264 + aoff + kk + ks*16 + 2*tg];
                a[mm][0] = ldu32(ap);        a[mm][1] = ldu32(ap + 8*264);
                a[mm][2] = ldu32(ap + 8);    a[mm][3] = ldu32(ap + 8*264 + 8);
            }
            #pragma unroll
            for (int nn = 0; nn < 4; nn++){
                const __half* bp = &Bb[(wn*32 + nn*8 + gq)*72 + ks*16 + 2*tg];
                uint32_t b0 = ldu32(bp), b1 = ldu32(bp + 8);
                #pragma unroll
                for (int mm = 0; mm < 2; mm++)
                    mma16(acc[mm][nn], a[mm][0],a[mm][1],a[mm][2],a[mm][3], b0, b1);
            }
        }
        __syncthreads();
        if (c + 2 < nch) fill(s, (c + 2)*64);
    }
}

template<int MODE>
__device__ __forceinline__ void store_out(float (&acc)[2][4][4], const float* __restrict__ bias,
                                          __half* __restrict__ stg, __half* __restrict__ dst,
                                          int r0, int t, int wm, int wn, int gq, int tg){
    #pragma unroll
    for (int mm = 0; mm < 2; mm++) for (int nn = 0; nn < 4; nn++){
        int row = wm*32 + mm*16 + gq, col = wn*32 + nn*8 + 2*tg;
        float b0 = bias[col], b1 = bias[col+1];
        float v0 = acc[mm][nn][0] + b0, v1 = acc[mm][nn][1] + b1;
        float v2 = acc[mm][nn][2] + b0, v3 = acc[mm][nn][3] + b1;
        if (MODE == 1){
            v0 = 1.f/(1.f + expf(-v0)); v1 = 1.f/(1.f + expf(-v1));
            v2 = 1.f/(1.f + expf(-v2)); v3 = 1.f/(1.f + expf(-v3));
        }
        stg[col*72 + row]           = __float2half_rn(v0);
        stg[(col+1)*72 + row]       = __float2half_rn(v1);
        stg[col*72 + row + 8]       = __float2half_rn(v2);
        stg[(col+1)*72 + row + 8]   = __float2half_rn(v3);
    }
    __syncthreads();
    #pragma unroll
    for (int p = 0; p < 4; p++){
        int idx = t + p*256;
        int col = idx >> 3, m8 = idx & 7;
        *(uint4*)&dst[(size_t)col*MM + r0 + m8*8] = *(const uint4*)&stg[col*72 + m8*8];
    }
    __syncthreads();
}

__global__ __launch_bounds__(256)
void k1_proj(const float* __restrict__ pair){
    extern __shared__ char smc[];
    __half* A_h  = (__half*)smc;
    float*  xs32 = (float*)(smc + 64*264*2);
    __half* Bs   = (__half*)(smc + 64*264*2);

    int t = threadIdx.x;
    int r0 = blockIdx.x * 64;
    int lane = t & 31, warp = t >> 5;
    int gq = lane >> 2, tg = lane & 3;
    int wm = warp >> 2, wn = warp & 3;

    #pragma unroll
    for (int p = 0; p < 8; p++){
        int idx = t + p*256;
        int c4 = idx & 31, m = idx >> 5;
        cp16f(&xs32[m*132 + c4*4], &pair[(size_t)(r0 + m)*128 + c4*4]);
    }
    cp_commit(); cp_wait0();
    __syncthreads();

    for (int rr = 0; rr < 8; rr++){
        int m = warp*8 + rr;
        float s = 0.f, ss = 0.f;
        #pragma unroll
        for (int q = 0; q < 4; q++){ float v = xs32[m*132 + lane + q*32]; s += v; ss += v*v; }
        #pragma unroll
        for (int o = 16; o > 0; o >>= 1){ s += __shfl_xor_sync(~0u, s, o); ss += __shfl_xor_sync(~0u, ss, o); }
        float mean = s * (1.f/128.f);
        float var  = ss * (1.f/128.f) - mean*mean;
        float inv  = rsqrtf(var + 1e-5f);
        #pragma unroll
        for (int q = 0; q < 4; q++){
            int c = lane + q*32;
            float v = xs32[m*132 + c];
            A_h[m*264 + c]       = __float2half_rn((v - mean) * inv);
            A_h[m*264 + 128 + c] = __float2half_rn(v);
        }
    }
    __syncthreads();

    float acc[2][4][4];

    #pragma unroll
    for (int a=0;a<2;a++) for (int b=0;b<4;b++) for (int c=0;c<4;c++) acc[a][b][c]=0.f;
    gemm16(g_WL, 256, 4, 0, Bs, A_h, acc, t, wm, wn, gq, tg);
    store_out<0>(acc, g_bL, Bs, g_left, r0, t, wm, wn, gq, tg);

    #pragma unroll
    for (int a=0;a<2;a++) for (int b=0;b<4;b++) for (int c=0;c<4;c++) acc[a][b][c]=0.f;
    gemm16(g_WR, 128, 2, 0, Bs, A_h, acc, t, wm, wn, gq, tg);
    store_out<0>(acc, g_bR, Bs, g_right, r0, t, wm, wn, gq, tg);

    #pragma unroll
    for (int a=0;a<2;a++) for (int b=0;b<4;b++) for (int c=0;c<4;c++) acc[a][b][c]=0.f;
    gemm16(g_WG, 128, 2, 128, Bs, A_h, acc, t, wm, wn, gq, tg);
    store_out<1>(acc, g_bG, Bs, g_gate, r0, t, wm, wn, gq, tg);
}

// ---------------- kernel 2 (round-11, .cg streaming fills) ----------------
#define K2_SMEM (2*128*72*2 + 2*64*136*2)

__global__ __launch_bounds__(256)
void k2_tri(){
    extern __shared__ char smc[];
    __half* As = (__half*)smc;                    // 2 * 128*72
    __half* Bs = (__half*)(smc + 2*128*72*2);     // 2 * 64*136
    __half* stg = (__half*)smc;                   // reused: 128*144

    int t = threadIdx.x;
    int lane = t & 31, warp = t >> 5;
    int gq = lane >> 2, tg = lane & 3;
    int wm = warp >> 2, wn = warp & 3;

    int h = blockIdx.z, i0 = blockIdx.y*128, j0 = blockIdx.x*128;
    const __half* L = g_left  + (size_t)h*MM;
    const __half* R = g_right + (size_t)h*MM;

    uint32_t as_base = (uint32_t)__cvta_generic_to_shared(As);
    uint32_t bs_base = (uint32_t)__cvta_generic_to_shared(Bs);

    float acc[4][4][4];
    #pragma unroll
    for (int a=0;a<4;a++) for (int b=0;b<4;b++) for (int c=0;c<4;c++) acc[a][b][c]=0.f;

    auto fill = [&](int s, int kk){
        #pragma unroll
        for (int p = 0; p < 4; p++){
            int idx = t + p*256;
            int r = idx >> 3, q = idx & 7;
            cp16hg(&As[s*128*72 + r*72 + q*8], &L[(size_t)(i0 + r)*384 + kk + q*8]);
        }
        #pragma unroll
        for (int p = 0; p < 4; p++){
            int idx = t + p*256;
            int kr = idx >> 4, q = idx & 15;
            cp16hg(&Bs[s*64*136 + kr*136 + q*8], &R[(size_t)(kk + kr)*384 + j0 + q*8]);
        }
        cp_commit();
    };

    fill(0, 0);
    fill(1, 64);

    int aRow = lane & 15, aKq = (lane >> 4) << 3;
    int bK   = lane & 15;

    for (int c = 0; c < 6; c++){
        int s = c & 1;
        if (c < 5) cp_wait1(); else cp_wait0();
        __syncthreads();
        uint32_t Ab_s = as_base + (uint32_t)(s*128*72*2);
        uint32_t Bb_s = bs_base + (uint32_t)(s*64*136*2);
        #pragma unroll
        for (int ks = 0; ks < 4; ks++){
            int k0 = ks*16;
            uint32_t a[4][4], b[4][2];
            #pragma unroll
            for (int mm = 0; mm < 4; mm++){
                uint32_t sa = Ab_s + (uint32_t)(((wm*64 + mm*16 + aRow)*72 + k0 + aKq)*2);
                ldm_x4(a[mm][0], a[mm][1], a[mm][2], a[mm][3], sa);
            }
            #pragma unroll
            for (int nn = 0; nn < 4; nn++){
                uint32_t sb = Bb_s + (uint32_t)(((k0 + bK)*136 + wn*32 + nn*8)*2);
                ldm_x2t(b[nn][0], b[nn][1], sb);
            }
            #pragma unroll
            for (int mm = 0; mm < 4; mm++)
                #pragma unroll
                for (int nn = 0; nn < 4; nn++)
                    mma16(acc[mm][nn], a[mm][0],a[mm][1],a[mm][2],a[mm][3],
                          b[nn][0], b[nn][1]);
        }
        __syncthreads();
        if (c + 2 < 6) fill(s, (c + 2)*64);
    }

    #pragma unroll
    for (int mm = 0; mm < 4; mm++) for (int nn = 0; nn < 4; nn++){
        int row = wm*64 + mm*16 + gq;
        int col = wn*32 + nn*8 + 2*tg;
        stg[row*144 + col]         = __float2half_rn(acc[mm][nn][0]);
        stg[row*144 + col + 1]     = __float2half_rn(acc[mm][nn][1]);
        stg[(row+8)*144 + col]     = __float2half_rn(acc[mm][nn][2]);
        stg[(row+8)*144 + col + 1] = __float2half_rn(acc[mm][nn][3]);
    }
    __syncthreads();

    __half* G = g_gate + (size_t)h*MM;
    #pragma unroll
    for (int p = 0; p < 8; p++){
        int idx = t + p*256;
        int row = idx >> 4, c8 = idx & 15;
        __half* gp = &G[(size_t)(i0 + row)*384 + j0 + c8*8];
        uint4 sv = *(const uint4*)&stg[row*144 + c8*8];
        uint4 gv = *(const uint4*)gp;
        const __half2* s2 = (const __half2*)&sv;
        const __half2* g2 = (const __half2*)&gv;
        uint4 ov;
        __half2* o2 = (__half2*)&ov;
        #pragma unroll
        for (int q = 0; q < 4; q++){
            float2 sf = __half22float2(s2[q]);
            float2 gf = __half22float2(g2[q]);
            o2[q] = __floats2half2_rn(sf.x * gf.x, sf.y * gf.y);
        }
        *(uint4*)gp = ov;
    }
}

// ---------------- kernel 3: round-11 mainloop + smem-staged residual epilogue ----------------
#define K3_SMEM (64*133*4 + 512)

__global__ __launch_bounds__(256)
void k3_out(const float* __restrict__ pair,
            const float* __restrict__ bo,   const float* __restrict__ gout,
            const float* __restrict__ bout, float* __restrict__ out){
    extern __shared__ char smc[];
    __half* As = (__half*)smc;                    // 2 * 32*72
    __half* Bs = (__half*)(smc + 2*32*72*2);      // 2 * 128*40
    float* stage = (float*)smc;                   // epilogue overlay, stride 132

    int t = threadIdx.x;
    int r0b = blockIdx.x * 64;
    int lane = t & 31, warp = t >> 5;
    int gq = lane >> 2, tg = lane & 3;
    int wm = warp >> 2, wn = warp & 3;
    const __half* O = g_gate;

    uint32_t as_base = (uint32_t)__cvta_generic_to_shared(As);

    float acc[2][4][4];
    #pragma unroll
    for (int a=0;a<2;a++) for (int b=0;b<4;b++) for (int c=0;c<4;c++) acc[a][b][c]=0.f;

    auto fill = [&](int s, int kk){
        {
            int kl = t >> 3, m8 = t & 7;
            cp16hg(&As[s*32*72 + kl*72 + m8*8], &O[(size_t)(kk + kl)*MM + r0b + m8*8]);
        }
        #pragma unroll
        for (int p = 0; p < 2; p++){
            int idx = t + p*256;
            int n = idx >> 2, q = idx & 3;
            cp16h(&Bs[s*128*40 + n*40 + q*8], &g_WoT[(size_t)n*128 + kk + q*8]);
        }
        cp_commit();
    };

    fill(0, 0);
    fill(1, 32);

    int quad = lane >> 3, qi = lane & 7;
    int aK = ((quad >> 1) << 3) + qi;
    int aM = (quad & 1) << 3;

    for (int c = 0; c < 4; c++){
        int s = c & 1;
        if (c < 3) cp_wait1(); else cp_wait0();
        __syncthreads();
        uint32_t Ab_s = as_base + (uint32_t)(s*32*72*2);
        const __half* Bb = &Bs[s*128*40];
        #pragma unroll
        for (int ks = 0; ks < 2; ks++){
            int k0 = ks*16;
            uint32_t a[2][4], b[4][2];
            #pragma unroll
            for (int mm = 0; mm < 2; mm++){
                uint32_t sa = Ab_s + (uint32_t)(((k0 + aK)*72 + wm*32 + mm*16 + aM)*2);
                ldm_x4t(a[mm][0], a[mm][1], a[mm][2], a[mm][3], sa);
            }
            #pragma unroll
            for (int nn = 0; nn < 4; nn++){
                const __half* bp = &Bb[(wn*32 + nn*8 + gq)*40 + ks*16 + 2*tg];
                b[nn][0] = ldu32(bp);  b[nn][1] = ldu32(bp + 8);
            }
            #pragma unroll
            for (int mm = 0; mm < 2; mm++)
                #pragma unroll
                for (int nn = 0; nn < 4; nn++)
                    mma16(acc[mm][nn], a[mm][0],a[mm][1],a[mm][2],a[mm][3],
                          b[nn][0], b[nn][1]);
        }
        __syncthreads();
        if (c + 2 < 4) fill(s, (c + 2)*32);
    }
    __syncthreads();

    // coalesced pair residual load into stage (As/Bs dead now)
    #pragma unroll
    for (int p = 0; p < 8; p++){
        int idx = t + p*256;
        int c4 = idx & 31, m = idx >> 5;
        cp16f(&stage[m*132 + c4*4], &pair[(size_t)(r0b + m)*128 + c4*4]);
    }
    cp_commit(); cp_wait0();
    __syncthreads();

    // scattered smem RMW: stage += acc + bias
    #pragma unroll
    for (int mm = 0; mm < 2; mm++) for (int nn = 0; nn < 4; nn++){
        int row = wm*32 + mm*16 + gq, col = wn*32 + nn*8 + 2*tg;
        stage[row*132 + col]         += acc[mm][nn][0] + bo[col];
        stage[row*132 + col + 1]     += acc[mm][nn][1] + bo[col+1];
        stage[(row+8)*132 + col]     += acc[mm][nn][2] + bo[col];
        stage[(row+8)*132 + col + 1] += acc[mm][nn][3] + bo[col+1];
    }
    __syncthreads();

    for (int rr = 0; rr < 8; rr++){
        int m = warp*8 + rr;
        float s = 0.f, ss = 0.f;
        #pragma unroll
        for (int q = 0; q < 4; q++){ float v = stage[m*132 + lane + q*32]; s += v; ss += v*v; }
        #pragma unroll
        for (int o = 16; o > 0; o >>= 1){ s += __shfl_xor_sync(~0u, s, o); ss += __shfl_xor_sync(~0u, ss, o); }
        float mean = s * (1.f/128.f);
        float var  = ss * (1.f/128.f) - mean*mean;
        float inv  = rsqrtf(var + 1e-5f);
        #pragma unroll
        for (int q = 0; q < 4; q++){
            int c = lane + q*32;
            out[(size_t)(r0b + m)*128 + c] = (stage[m*132 + c] - mean) * inv * gout[c] + bout[c];
        }
    }
}

// ---------------- launch ----------------
extern "C" void kernel_launch(void* const* d_in, const int* in_sizes, int n_in,
                              void* d_out, int out_size){
    const float* pair   = (const float*)d_in[0];
    const float* g_l    = (const float*)d_in[1];
    const float* b_l    = (const float*)d_in[2];
    const float* g_r    = (const float*)d_in[3];
    const float* b_r    = (const float*)d_in[4];
    const float* g_o    = (const float*)d_in[5];
    const float* b_o    = (const float*)d_in[6];
    const float* W_l    = (const float*)d_in[7];
    const float* bias_l = (const float*)d_in[8];
    const float* W_r    = (const float*)d_in[9];
    const float* bias_r = (const float*)d_in[10];
    const float* W_g    = (const float*)d_in[11];
    const float* bias_g = (const float*)d_in[12];
    const float* W_e    = (const float*)d_in[13];
    const float* bias_e = (const float*)d_in[14];
    const float* W_o    = (const float*)d_in[15];
    const float* bias_o = (const float*)d_in[16];
    float* out = (float*)d_out;

    cudaFuncSetAttribute(k1_proj, cudaFuncAttributeMaxDynamicSharedMemorySize, K1_SMEM);
    cudaFuncSetAttribute(k2_tri,  cudaFuncAttributeMaxDynamicSharedMemorySize, K2_SMEM);
    cudaFuncSetAttribute(k3_out,  cudaFuncAttributeMaxDynamicSharedMemorySize, K3_SMEM);

    prep_kernel<<<128, 128>>>(W_l, bias_l, W_r, bias_r, W_g, bias_g, W_e, bias_e,
                              g_l, b_l, g_r, b_r, W_o);
    k1_proj<<<MM/64, 256, K1_SMEM>>>(pair);
    k2_tri<<<dim3(3, 3, 128), 256, K2_SMEM>>>();
    k3_out<<<MM/64, 256, K3_SMEM>>>(pair, bias_o, g_o, b_o, out);
}

// round 16
// speedup vs baseline: 1.1119x; 1.0267x over previous
#include <cuda_runtime.h>
#include <cuda_fp16.h>
#include <cstdint>

#define CC 128
#define HH 128
#define MM (384*384)

__device__ __align__(16) __half g_left [(size_t)HH*MM];   // [h][i*384+k]
__device__ __align__(16) __half g_right[(size_t)HH*MM];   // [h][k*384+j]
__device__ __align__(16) __half g_gate [(size_t)HH*MM];   // [h][i*384+j]; k2 overwrites in-place
__device__ __align__(16) __half g_WL [128*256];
__device__ __align__(16) __half g_WR [128*128];
__device__ __align__(16) __half g_WG [128*128];
__device__ __align__(16) __half g_WoT[128*128];
__device__ float g_bL[128], g_bR[128], g_bG[128];

__device__ __forceinline__ void mma16(float* d, uint32_t a0,uint32_t a1,uint32_t a2,uint32_t a3,
                                      uint32_t b0,uint32_t b1){
    asm volatile(
      "mma.sync.aligned.m16n8k16.row.col.f32.f16.f16.f32 "
      "{%0,%1,%2,%3},{%4,%5,%6,%7},{%8,%9},{%0,%1,%2,%3};\n"
      : "+f"(d[0]),"+f"(d[1]),"+f"(d[2]),"+f"(d[3])
      : "r"(a0),"r"(a1),"r"(a2),"r"(a3),"r"(b0),"r"(b1));
}
__device__ __forceinline__ void cp16h(__half* s, const __half* g){
    unsigned sa = (unsigned)__cvta_generic_to_shared(s);
    asm volatile("cp.async.ca.shared.global [%0], [%1], 16;" :: "r"(sa), "l"(g) : "memory");
}
__device__ __forceinline__ void cp16hg(__half* s, const __half* g){   // L1-bypass streaming
    unsigned sa = (unsigned)__cvta_generic_to_shared(s);
    asm volatile("cp.async.cg.shared.global [%0], [%1], 16;" :: "r"(sa), "l"(g) : "memory");
}
__device__ __forceinline__ void cp16f(float* s, const float* g){
    unsigned sa = (unsigned)__cvta_generic_to_shared(s);
    asm volatile("cp.async.ca.shared.global [%0], [%1], 16;" :: "r"(sa), "l"(g) : "memory");
}
__device__ __forceinline__ void cp16fg(float* s, const float* g){     // L1-bypass streaming
    unsigned sa = (unsigned)__cvta_generic_to_shared(s);
    asm volatile("cp.async.cg.shared.global [%0], [%1], 16;" :: "r"(sa), "l"(g) : "memory");
}
__device__ __forceinline__ void cp_commit(){ asm volatile("cp.async.commit_group;" ::: "memory"); }
__device__ __forceinline__ void cp_wait1(){ asm volatile("cp.async.wait_group 1;" ::: "memory"); }
__device__ __forceinline__ void cp_wait0(){ asm volatile("cp.async.wait_group 0;" ::: "memory"); }
__device__ __forceinline__ uint32_t ldu32(const __half* p){ return *(const uint32_t*)p; }
__device__ __forceinline__ void ldm_x4(uint32_t& r0, uint32_t& r1, uint32_t& r2, uint32_t& r3, uint32_t sa){
    asm volatile("ldmatrix.sync.aligned.m8n8.x4.shared.b16 {%0,%1,%2,%3}, [%4];"
                 : "=r"(r0),"=r"(r1),"=r"(r2),"=r"(r3) : "r"(sa));
}
__device__ __forceinline__ void ldm_x4t(uint32_t& r0, uint32_t& r1, uint32_t& r2, uint32_t& r3, uint32_t sa){
    asm volatile("ldmatrix.sync.aligned.m8n8.x4.trans.shared.b16 {%0,%1,%2,%3}, [%4];"
                 : "=r"(r0),"=r"(r1),"=r"(r2),"=r"(r3) : "r"(sa));
}
__device__ __forceinline__ void ldm_x2t(uint32_t& r0, uint32_t& r1, uint32_t sa){
    asm volatile("ldmatrix.sync.aligned.m8n8.x2.trans.shared.b16 {%0,%1}, [%2];"
                 : "=r"(r0),"=r"(r1) : "r"(sa));
}

// ---------------- prep ----------------
__global__ void prep_kernel(const float* __restrict__ Wl, const float* __restrict__ bl,
                            const float* __restrict__ Wr, const float* __restrict__ br,
                            const float* __restrict__ Wg, const float* __restrict__ bg,
                            const float* __restrict__ We, const float* __restrict__ be,
                            const float* __restrict__ gl, const float* __restrict__ bL,
                            const float* __restrict__ gr, const float* __restrict__ bR,
                            const float* __restrict__ Wo){
    __shared__ float redL[4], redR[4];
    int h = blockIdx.x, c = threadIdx.x;
    int lane = c & 31, warp = c >> 5;
    float wl = Wl[c*128 + h], wr = Wr[c*128 + h];
    g_WL[h*256 + c]       = __float2half_rn(gl[c] * wl);
    g_WL[h*256 + 128 + c] = __float2half_rn(We[c*128 + h]);
    g_WR[h*128 + c]       = __float2half_rn(gr[c] * wr);
    g_WG[h*128 + c]       = __float2half_rn(Wg[c*128 + h]);
    g_WoT[c*128 + h]      = __float2half_rn(Wo[h*128 + c]);
    float pl = bL[c] * wl, pr = bR[c] * wr;
    #pragma unroll
    for (int o = 16; o > 0; o >>= 1){
        pl += __shfl_xor_sync(~0u, pl, o);
        pr += __shfl_xor_sync(~0u, pr, o);
    }
    if (lane == 0){ redL[warp] = pl; redR[warp] = pr; }
    __syncthreads();
    if (c == 0){
        g_bL[h] = bl[h] + be[h] + redL[0]+redL[1]+redL[2]+redL[3];
        g_bR[h] = br[h] + redR[0]+redR[1]+redR[2]+redR[3];
        g_bG[h] = bg[h];
    }
}

// ---------------- kernel 1 ----------------
#define K1_SMEM (64*264*2 + 2*128*72*2)

__device__ __forceinline__ void gemm16(const __half* __restrict__ Wsrc, int rsW, int nch, int aoff,
                                       __half* __restrict__ Bs, const __half* __restrict__ A_h,
                                       float (&acc)[2][4][4],
                                       int t, int wm, int wn, int gq, int tg){
    auto fill = [&](int s, int kk){
        #pragma unroll
        for (int p = 0; p < 4; p++){
            int idx = t + p*256;
            int r = idx >> 3, q = idx & 7;
            cp16h(&Bs[s*128*72 + r*72 + q*8], &Wsrc[(size_t)r*rsW + kk + q*8]);
        }
        cp_commit();
    };
    fill(0, 0);
    if (nch > 1) fill(1, 64);
    for (int c = 0; c < nch; c++){
        int s = c & 1;
        if (c + 1 < nch) cp_wait1(); else cp_wait0();
        __syncthreads();
        const __half* Bb = &Bs[s*128*72];
        int kk = c*64;
        #pragma unroll
        for (int ks = 0; ks < 4; ks++){
            uint32_t a[2][4];
            #pragma unroll
            for (int mm = 0; mm < 2; mm++){
                const __half* ap = &A_h[(wm*32 + mm*16 + gq)*264 + aoff + kk + ks*16 + 2*tg];
                a[mm][0] = ldu32(ap);        a[mm][1] = ldu32(ap + 8*264);
                a[mm][2] = ldu32(ap + 8);    a[mm][3] = ldu32(ap + 8*264 + 8);
            }
            #pragma unroll
            for (int nn = 0; nn < 4; nn++){
                const __half* bp = &Bb[(wn*32 + nn*8 + gq)*72 + ks*16 + 2*tg];
                uint32_t b0 = ldu32(bp), b1 = ldu32(bp + 8);
                #pragma unroll
                for (int mm = 0; mm < 2; mm++)
                    mma16(acc[mm][nn], a[mm][0],a[mm][1],a[mm][2],a[mm][3], b0, b1);
            }
        }
        __syncthreads();
        if (c + 2 < nch) fill(s, (c + 2)*64);
    }
}

template<int MODE>
__device__ __forceinline__ void store_out(float (&acc)[2][4][4], const float* __restrict__ bias,
                                          __half* __restrict__ stg, __half* __restrict__ dst,
                                          int r0, int t, int wm, int wn, int gq, int tg){
    #pragma unroll
    for (int mm = 0; mm < 2; mm++) for (int nn = 0; nn < 4; nn++){
        int row = wm*32 + mm*16 + gq, col = wn*32 + nn*8 + 2*tg;
        float b0 = bias[col], b1 = bias[col+1];
        float v0 = acc[mm][nn][0] + b0, v1 = acc[mm][nn][1] + b1;
        float v2 = acc[mm][nn][2] + b0, v3 = acc[mm][nn][3] + b1;
        if (MODE == 1){
            v0 = 1.f/(1.f + expf(-v0)); v1 = 1.f/(1.f + expf(-v1));
            v2 = 1.f/(1.f + expf(-v2)); v3 = 1.f/(1.f + expf(-v3));
        }
        stg[col*72 + row]           = __float2half_rn(v0);
        stg[(col+1)*72 + row]       = __float2half_rn(v1);
        stg[col*72 + row + 8]       = __float2half_rn(v2);
        stg[(col+1)*72 + row + 8]   = __float2half_rn(v3);
    }
    __syncthreads();
    #pragma unroll
    for (int p = 0; p < 4; p++){
        int idx = t + p*256;
        int col = idx >> 3, m8 = idx & 7;
        *(uint4*)&dst[(size_t)col*MM + r0 + m8*8] = *(const uint4*)&stg[col*72 + m8*8];
    }
    __syncthreads();
}

__global__ __launch_bounds__(256)
void k1_proj(const float* __restrict__ pair){
    extern __shared__ char smc[];
    __half* A_h  = (__half*)smc;
    float*  xs32 = (float*)(smc + 64*264*2);
    __half* Bs   = (__half*)(smc + 64*264*2);

    int t = threadIdx.x;
    int r0 = blockIdx.x * 64;
    int lane = t & 31, warp = t >> 5;
    int gq = lane >> 2, tg = lane & 3;
    int wm = warp >> 2, wn = warp & 3;

    #pragma unroll
    for (int p = 0; p < 8; p++){
        int idx = t + p*256;
        int c4 = idx & 31, m = idx >> 5;
        cp16fg(&xs32[m*132 + c4*4], &pair[(size_t)(r0 + m)*128 + c4*4]);
    }
    cp_commit(); cp_wait0();
    __syncthreads();

    for (int rr = 0; rr < 8; rr++){
        int m = warp*8 + rr;
        float s = 0.f, ss = 0.f;
        #pragma unroll
        for (int q = 0; q < 4; q++){ float v = xs32[m*132 + lane + q*32]; s += v; ss += v*v; }
        #pragma unroll
        for (int o = 16; o > 0; o >>= 1){ s += __shfl_xor_sync(~0u, s, o); ss += __shfl_xor_sync(~0u, ss, o); }
        float mean = s * (1.f/128.f);
        float var  = ss * (1.f/128.f) - mean*mean;
        float inv  = rsqrtf(var + 1e-5f);
        #pragma unroll
        for (int q = 0; q < 4; q++){
            int c = lane + q*32;
            float v = xs32[m*132 + c];
            A_h[m*264 + c]       = __float2half_rn((v - mean) * inv);
            A_h[m*264 + 128 + c] = __float2half_rn(v);
        }
    }
    __syncthreads();

    float acc[2][4][4];

    #pragma unroll
    for (int a=0;a<2;a++) for (int b=0;b<4;b++) for (int c=0;c<4;c++) acc[a][b][c]=0.f;
    gemm16(g_WL, 256, 4, 0, Bs, A_h, acc, t, wm, wn, gq, tg);
    store_out<0>(acc, g_bL, Bs, g_left, r0, t, wm, wn, gq, tg);

    #pragma unroll
    for (int a=0;a<2;a++) for (int b=0;b<4;b++) for (int c=0;c<4;c++) acc[a][b][c]=0.f;
    gemm16(g_WR, 128, 2, 0, Bs, A_h, acc, t, wm, wn, gq, tg);
    store_out<0>(acc, g_bR, Bs, g_right, r0, t, wm, wn, gq, tg);

    #pragma unroll
    for (int a=0;a<2;a++) for (int b=0;b<4;b++) for (int c=0;c<4;c++) acc[a][b][c]=0.f;
    gemm16(g_WG, 128, 2, 128, Bs, A_h, acc, t, wm, wn, gq, tg);
    store_out<1>(acc, g_bG, Bs, g_gate, r0, t, wm, wn, gq, tg);
}

// ---------------- kernel 2 ----------------
#define K2_SMEM (2*128*72*2 + 2*64*136*2)

__global__ __launch_bounds__(256)
void k2_tri(){
    extern __shared__ char smc[];
    __half* As = (__half*)smc;                    // 2 * 128*72
    __half* Bs = (__half*)(smc + 2*128*72*2);     // 2 * 64*136
    __half* stg = (__half*)smc;                   // reused: 128*144

    int t = threadIdx.x;
    int lane = t & 31, warp = t >> 5;
    int gq = lane >> 2, tg = lane & 3;
    int wm = warp >> 2, wn = warp & 3;

    int h = blockIdx.z, i0 = blockIdx.y*128, j0 = blockIdx.x*128;
    const __half* L = g_left  + (size_t)h*MM;
    const __half* R = g_right + (size_t)h*MM;

    uint32_t as_base = (uint32_t)__cvta_generic_to_shared(As);
    uint32_t bs_base = (uint32_t)__cvta_generic_to_shared(Bs);

    float acc[4][4][4];
    #pragma unroll
    for (int a=0;a<4;a++) for (int b=0;b<4;b++) for (int c=0;c<4;c++) acc[a][b][c]=0.f;

    auto fill = [&](int s, int kk){
        #pragma unroll
        for (int p = 0; p < 4; p++){
            int idx = t + p*256;
            int r = idx >> 3, q = idx & 7;
            cp16hg(&As[s*128*72 + r*72 + q*8], &L[(size_t)(i0 + r)*384 + kk + q*8]);
        }
        #pragma unroll
        for (int p = 0; p < 4; p++){
            int idx = t + p*256;
            int kr = idx >> 4, q = idx & 15;
            cp16hg(&Bs[s*64*136 + kr*136 + q*8], &R[(size_t)(kk + kr)*384 + j0 + q*8]);
        }
        cp_commit();
    };

    fill(0, 0);
    fill(1, 64);

    int aRow = lane & 15, aKq = (lane >> 4) << 3;
    int bK   = lane & 15;

    for (int c = 0; c < 6; c++){
        int s = c & 1;
        if (c < 5) cp_wait1(); else cp_wait0();
        __syncthreads();
        uint32_t Ab_s = as_base + (uint32_t)(s*128*72*2);
        uint32_t Bb_s = bs_base + (uint32_t)(s*64*136*2);
        #pragma unroll
        for (int ks = 0; ks < 4; ks++){
            int k0 = ks*16;
            uint32_t a[4][4], b[4][2];
            #pragma unroll
            for (int mm = 0; mm < 4; mm++){
                uint32_t sa = Ab_s + (uint32_t)(((wm*64 + mm*16 + aRow)*72 + k0 + aKq)*2);
                ldm_x4(a[mm][0], a[mm][1], a[mm][2], a[mm][3], sa);
            }
            #pragma unroll
            for (int nn = 0; nn < 4; nn++){
                uint32_t sb = Bb_s + (uint32_t)(((k0 + bK)*136 + wn*32 + nn*8)*2);
                ldm_x2t(b[nn][0], b[nn][1], sb);
            }
            #pragma unroll
            for (int mm = 0; mm < 4; mm++)
                #pragma unroll
                for (int nn = 0; nn < 4; nn++)
                    mma16(acc[mm][nn], a[mm][0],a[mm][1],a[mm][2],a[mm][3],
                          b[nn][0], b[nn][1]);
        }
        __syncthreads();
        if (c + 2 < 6) fill(s, (c + 2)*64);
    }

    #pragma unroll
    for (int mm = 0; mm < 4; mm++) for (int nn = 0; nn < 4; nn++){
        int row = wm*64 + mm*16 + gq;
        int col = wn*32 + nn*8 + 2*tg;
        stg[row*144 + col]         = __float2half_rn(acc[mm][nn][0]);
        stg[row*144 + col + 1]     = __float2half_rn(acc[mm][nn][1]);
        stg[(row+8)*144 + col]     = __float2half_rn(acc[mm][nn][2]);
        stg[(row+8)*144 + col + 1] = __float2half_rn(acc[mm][nn][3]);
    }
    __syncthreads();

    __half* G = g_gate + (size_t)h*MM;
    #pragma unroll
    for (int p = 0; p < 8; p++){
        int idx = t + p*256;
        int row = idx >> 4, c8 = idx & 15;
        __half* gp = &G[(size_t)(i0 + row)*384 + j0 + c8*8];
        uint4 sv = *(const uint4*)&stg[row*144 + c8*8];
        uint4 gv = *(const uint4*)gp;
        const __half2* s2 = (const __half2*)&sv;
        const __half2* g2 = (const __half2*)&gv;
        uint4 ov;
        __half2* o2 = (__half2*)&ov;
        #pragma unroll
        for (int q = 0; q < 4; q++){
            float2 sf = __half22float2(s2[q]);
            float2 gf = __half22float2(g2[q]);
            o2[q] = __floats2half2_rn(sf.x * gf.x, sf.y * gf.y);
        }
        *(uint4*)gp = ov;
    }
}

// ---------------- kernel 3 ----------------
#define K3_SMEM (64*133*4 + 512)

__global__ __launch_bounds__(256, 4)
void k3_out(const float* __restrict__ pair,
            const float* __restrict__ bo,   const float* __restrict__ gout,
            const float* __restrict__ bout, float* __restrict__ out){
    extern __shared__ char smc[];
    __half* As = (__half*)smc;                    // 2 * 32*72
    __half* Bs = (__half*)(smc + 2*32*72*2);      // 2 * 128*40
    float* stage = (float*)smc;                   // epilogue overlay, stride 132

    int t = threadIdx.x;
    int r0b = blockIdx.x * 64;
    int lane = t & 31, warp = t >> 5;
    int gq = lane >> 2, tg = lane & 3;
    int wm = warp >> 2, wn = warp & 3;
    const __half* O = g_gate;

    uint32_t as_base = (uint32_t)__cvta_generic_to_shared(As);

    float acc[2][4][4];
    #pragma unroll
    for (int a=0;a<2;a++) for (int b=0;b<4;b++) for (int c=0;c<4;c++) acc[a][b][c]=0.f;

    auto fill = [&](int s, int kk){
        {
            int kl = t >> 3, m8 = t & 7;
            cp16hg(&As[s*32*72 + kl*72 + m8*8], &O[(size_t)(kk + kl)*MM + r0b + m8*8]);
        }
        #pragma unroll
        for (int p = 0; p < 2; p++){
            int idx = t + p*256;
            int n = idx >> 2, q = idx & 3;
            cp16h(&Bs[s*128*40 + n*40 + q*8], &g_WoT[(size_t)n*128 + kk + q*8]);
        }
        cp_commit();
    };

    fill(0, 0);
    fill(1, 32);

    int quad = lane >> 3, qi = lane & 7;
    int aK = ((quad >> 1) << 3) + qi;
    int aM = (quad & 1) << 3;

    for (int c = 0; c < 4; c++){
        int s = c & 1;
        if (c < 3) cp_wait1(); else cp_wait0();
        __syncthreads();
        uint32_t Ab_s = as_base + (uint32_t)(s*32*72*2);
        const __half* Bb = &Bs[s*128*40];
        #pragma unroll
        for (int ks = 0; ks < 2; ks++){
            int k0 = ks*16;
            uint32_t a[2][4], b[4][2];
            #pragma unroll
            for (int mm = 0; mm < 2; mm++){
                uint32_t sa = Ab_s + (uint32_t)(((k0 + aK)*72 + wm*32 + mm*16 + aM)*2);
                ldm_x4t(a[mm][0], a[mm][1], a[mm][2], a[mm][3], sa);
            }
            #pragma unroll
            for (int nn = 0; nn < 4; nn++){
                const __half* bp = &Bb[(wn*32 + nn*8 + gq)*40 + ks*16 + 2*tg];
                b[nn][0] = ldu32(bp);  b[nn][1] = ldu32(bp + 8);
            }
            #pragma unroll
            for (int mm = 0; mm < 2; mm++)
                #pragma unroll
                for (int nn = 0; nn < 4; nn++)
                    mma16(acc[mm][nn], a[mm][0],a[mm][1],a[mm][2],a[mm][3],
                          b[nn][0], b[nn][1]);
        }
        __syncthreads();
        if (c + 2 < 4) fill(s, (c + 2)*32);
    }
    __syncthreads();

    // coalesced pair residual load into stage (As/Bs dead now)
    #pragma unroll
    for (int p = 0; p < 8; p++){
        int idx = t + p*256;
        int c4 = idx & 31, m = idx >> 5;
        cp16fg(&stage[m*132 + c4*4], &pair[(size_t)(r0b + m)*128 + c4*4]);
    }
    cp_commit(); cp_wait0();
    __syncthreads();

    // scattered smem RMW: stage += acc + bias
    #pragma unroll
    for (int mm = 0; mm < 2; mm++) for (int nn = 0; nn < 4; nn++){
        int row = wm*32 + mm*16 + gq, col = wn*32 + nn*8 + 2*tg;
        stage[row*132 + col]         += acc[mm][nn][0] + bo[col];
        stage[row*132 + col + 1]     += acc[mm][nn][1] + bo[col+1];
        stage[(row+8)*132 + col]     += acc[mm][nn][2] + bo[col];
        stage[(row+8)*132 + col + 1] += acc[mm][nn][3] + bo[col+1];
    }
    __syncthreads();

    for (int rr = 0; rr < 8; rr++){
        int m = warp*8 + rr;
        float s = 0.f, ss = 0.f;
        #pragma unroll
        for (int q = 0; q < 4; q++){ float v = stage[m*132 + lane + q*32]; s += v; ss += v*v; }
        #pragma unroll
        for (int o = 16; o > 0; o >>= 1){ s += __shfl_xor_sync(~0u, s, o); ss += __shfl_xor_sync(~0u, ss, o); }
        float mean = s * (1.f/128.f);
        float var  = ss * (1.f/128.f) - mean*mean;
        float inv  = rsqrtf(var + 1e-5f);
        #pragma unroll
        for (int q = 0; q < 4; q++){
            int c = lane + q*32;
            out[(size_t)(r0b + m)*128 + c] = (stage[m*132 + c] - mean) * inv * gout[c] + bout[c];
        }
    }
}

// ---------------- launch ----------------
extern "C" void kernel_launch(void* const* d_in, const int* in_sizes, int n_in,
                              void* d_out, int out_size){
    const float* pair   = (const float*)d_in[0];
    const float* g_l    = (const float*)d_in[1];
    const float* b_l    = (const float*)d_in[2];
    const float* g_r    = (const float*)d_in[3];
    const float* b_r    = (const float*)d_in[4];
    const float* g_o    = (const float*)d_in[5];
    const float* b_o    = (const float*)d_in[6];
    const float* W_l    = (const float*)d_in[7];
    const float* bias_l = (const float*)d_in[8];
    const float* W_r    = (const float*)d_in[9];
    const float* bias_r = (const float*)d_in[10];
    const float* W_g    = (const float*)d_in[11];
    const float* bias_g = (const float*)d_in[12];
    const float* W_e    = (const float*)d_in[13];
    const float* bias_e = (const float*)d_in[14];
    const float* W_o    = (const float*)d_in[15];
    const float* bias_o = (const float*)d_in[16];
    float* out = (float*)d_out;

    cudaFuncSetAttribute(k1_proj, cudaFuncAttributeMaxDynamicSharedMemorySize, K1_SMEM);
    cudaFuncSetAttribute(k2_tri,  cudaFuncAttributeMaxDynamicSharedMemorySize, K2_SMEM);
    cudaFuncSetAttribute(k3_out,  cudaFuncAttributeMaxDynamicSharedMemorySize, K3_SMEM);

    prep_kernel<<<128, 128>>>(W_l, bias_l, W_r, bias_r, W_g, bias_g, W_e, bias_e,
                              g_l, b_l, g_r, b_r, W_o);
    k1_proj<<<MM/64, 256, K1_SMEM>>>(pair);
    k2_tri<<<dim3(3, 3, 128), 256, K2_SMEM>>>();
    k3_out<<<MM/64, 256, K3_SMEM>>>(pair, bias_o, g_o, b_o, out);
}